// round 5
// baseline (speedup 1.0000x reference)
#include <cuda_runtime.h>

// VQ nearest-codebook lookup + straight-through output, fp32x2 packed FFMA,
// LDS.128 codebook fetch, 16-way accumulator ILP.
// x:   [32, 64, 64, 64] fp32 (B, C, H, W) -> rows r = b*4096 + n
//      x element (r, c) at x[b*262144 + c*4096 + n] (coalesced across threads)
// emb: [512, 64] fp32
// out: flat [131072, 64] fp32 row-major

#define THREADS    256
#define CHUNK_ROWS 512         // 256 threads * 2 rows
#define GRID       128         // 2 chunks per block
#define KD4        16          // 64 / 4
typedef unsigned long long u64;

__device__ __forceinline__ void ffma2(u64 &d, u64 a, u64 b) {
    asm("fma.rn.f32x2 %0, %1, %2, %0;" : "+l"(d) : "l"(a), "l"(b));
}
__device__ __forceinline__ u64 pack2(float lo, float hi) {
    u64 v; asm("mov.b64 %0, {%1, %2};" : "=l"(v) : "f"(lo), "f"(hi)); return v;
}
__device__ __forceinline__ float hadd2(u64 v) {
    float lo, hi; asm("mov.b64 {%0, %1}, %2;" : "=f"(lo), "=f"(hi) : "l"(v));
    return lo + hi;
}

__global__ void __launch_bounds__(THREADS, 1)
vq_kernel(const float* __restrict__ x, const float* __restrict__ emb,
          float* __restrict__ out)
{
    extern __shared__ float smem[];
    float4*           es    = (float4*)smem;            // 512 * 16 float4 = 128 KB
    const ulonglong2* es128 = (const ulonglong2*)smem;  // same bytes, 2x f32x2 view
    float*            e_sq  = smem + 512 * 64;          // 512 floats

    const int tid = threadIdx.x;

    // Stage codebook into shared memory.
    const float4* ev = (const float4*)emb;
    #pragma unroll
    for (int i = tid; i < 512 * KD4; i += THREADS) es[i] = ev[i];
    __syncthreads();

    // Per-code squared norms.
    for (int c = tid; c < 512; c += THREADS) {
        float s = 0.0f;
        #pragma unroll
        for (int kk = 0; kk < KD4; kk++) {
            float4 e = es[c * KD4 + kk];
            s = fmaf(e.x, e.x, s); s = fmaf(e.y, e.y, s);
            s = fmaf(e.z, e.z, s); s = fmaf(e.w, e.w, s);
        }
        e_sq[c] = s;
    }
    __syncthreads();

    float4* outv = (float4*)out;

    #pragma unroll 1
    for (int ci = 0; ci < 2; ci++) {
        const int chunk = blockIdx.x * 2 + ci;
        const int r0 = chunk * CHUNK_ROWS + tid;
        const int r1 = r0 + THREADS;

        // Load both x rows into registers as 32 f32x2 pairs each.
        u64 x0p[32], x1p[32];
        {
            const int b0 = r0 >> 12, n0 = r0 & 4095;
            const int b1 = r1 >> 12, n1 = r1 & 4095;
            const float* xp0 = x + (size_t)b0 * 262144 + n0;
            const float* xp1 = x + (size_t)b1 * 262144 + n1;
            #pragma unroll
            for (int j = 0; j < 32; j++) {
                x0p[j] = pack2(xp0[(2*j)*4096], xp0[(2*j+1)*4096]);
                x1p[j] = pack2(xp1[(2*j)*4096], xp1[(2*j+1)*4096]);
            }
        }

        float best0 = 3.402823466e38f, best1 = 3.402823466e38f;
        int   bi0 = 0, bi1 = 0;

        // 4 codes x 2 rows per iter. Per j2-step: 4x LDS.128 + 16 FFMA2,
        // 16 independent accumulators (code x row x half).
        #pragma unroll 1
        for (int c = 0; c < 512; c += 4) {
            const ulonglong2* e0 = es128 + (size_t)c * 16;  // 16 x 16B per code
            const ulonglong2* e1 = e0 + 16;
            const ulonglong2* e2 = e0 + 32;
            const ulonglong2* e3 = e0 + 48;
            u64 a00a = 0, a00b = 0, a01a = 0, a01b = 0;
            u64 a02a = 0, a02b = 0, a03a = 0, a03b = 0;
            u64 a10a = 0, a10b = 0, a11a = 0, a11b = 0;
            u64 a12a = 0, a12b = 0, a13a = 0, a13b = 0;
            #pragma unroll
            for (int j2 = 0; j2 < 16; j2++) {
                ulonglong2 v0 = e0[j2];
                ulonglong2 v1 = e1[j2];
                ulonglong2 v2 = e2[j2];
                ulonglong2 v3 = e3[j2];
                u64 p0a = x0p[2*j2], p0b = x0p[2*j2+1];
                u64 p1a = x1p[2*j2], p1b = x1p[2*j2+1];
                ffma2(a00a, p0a, v0.x); ffma2(a01a, p0a, v1.x);
                ffma2(a02a, p0a, v2.x); ffma2(a03a, p0a, v3.x);
                ffma2(a10a, p1a, v0.x); ffma2(a11a, p1a, v1.x);
                ffma2(a12a, p1a, v2.x); ffma2(a13a, p1a, v3.x);
                ffma2(a00b, p0b, v0.y); ffma2(a01b, p0b, v1.y);
                ffma2(a02b, p0b, v2.y); ffma2(a03b, p0b, v3.y);
                ffma2(a10b, p1b, v0.y); ffma2(a11b, p1b, v1.y);
                ffma2(a12b, p1b, v2.y); ffma2(a13b, p1b, v3.y);
            }
            // Pairwise merge halves, then m = e_sq - 2*cross.
            // Ascending scan with strict '<' keeps first-index tie-breaking.
            float s0 = e_sq[c+0], s1 = e_sq[c+1], s2 = e_sq[c+2], s3 = e_sq[c+3];
            float m;
            m = fmaf(-2.0f, hadd2(a00a) + hadd2(a00b), s0); if (m < best0) { best0 = m; bi0 = c+0; }
            m = fmaf(-2.0f, hadd2(a01a) + hadd2(a01b), s1); if (m < best0) { best0 = m; bi0 = c+1; }
            m = fmaf(-2.0f, hadd2(a02a) + hadd2(a02b), s2); if (m < best0) { best0 = m; bi0 = c+2; }
            m = fmaf(-2.0f, hadd2(a03a) + hadd2(a03b), s3); if (m < best0) { best0 = m; bi0 = c+3; }
            m = fmaf(-2.0f, hadd2(a10a) + hadd2(a10b), s0); if (m < best1) { best1 = m; bi1 = c+0; }
            m = fmaf(-2.0f, hadd2(a11a) + hadd2(a11b), s1); if (m < best1) { best1 = m; bi1 = c+1; }
            m = fmaf(-2.0f, hadd2(a12a) + hadd2(a12b), s2); if (m < best1) { best1 = m; bi1 = c+2; }
            m = fmaf(-2.0f, hadd2(a13a) + hadd2(a13b), s3); if (m < best1) { best1 = m; bi1 = c+3; }
        }

        // Straight-through output: out = x + (q - x), replicated in fp32.
        #pragma unroll
        for (int kk = 0; kk < KD4; kk++) {
            float4 e = es[bi0 * KD4 + kk];
            float2 pl, ph;
            asm("mov.b64 {%0, %1}, %2;" : "=f"(pl.x), "=f"(pl.y) : "l"(x0p[2*kk]));
            asm("mov.b64 {%0, %1}, %2;" : "=f"(ph.x), "=f"(ph.y) : "l"(x0p[2*kk+1]));
            outv[(size_t)r0 * KD4 + kk] =
                make_float4(pl.x + (e.x - pl.x), pl.y + (e.y - pl.y),
                            ph.x + (e.z - ph.x), ph.y + (e.w - ph.y));
        }
        #pragma unroll
        for (int kk = 0; kk < KD4; kk++) {
            float4 e = es[bi1 * KD4 + kk];
            float2 pl, ph;
            asm("mov.b64 {%0, %1}, %2;" : "=f"(pl.x), "=f"(pl.y) : "l"(x1p[2*kk]));
            asm("mov.b64 {%0, %1}, %2;" : "=f"(ph.x), "=f"(ph.y) : "l"(x1p[2*kk+1]));
            outv[(size_t)r1 * KD4 + kk] =
                make_float4(pl.x + (e.x - pl.x), pl.y + (e.y - pl.y),
                            ph.x + (e.z - ph.x), ph.y + (e.w - ph.y));
        }
    }
}

extern "C" void kernel_launch(void* const* d_in, const int* in_sizes, int n_in,
                              void* d_out, int out_size)
{
    const float* x   = (const float*)d_in[0];   // 8388608 floats
    const float* emb = (const float*)d_in[1];   // 32768 floats
    float* out = (float*)d_out;                 // 8388608 floats

    const size_t smem = (512 * 64 + 512) * sizeof(float);   // 130 KB
    cudaFuncSetAttribute(vq_kernel,
                         cudaFuncAttributeMaxDynamicSharedMemorySize,
                         (int)smem);
    vq_kernel<<<GRID, THREADS, smem>>>(x, emb, out);
}

// round 7
// speedup vs baseline: 1.1782x; 1.1782x over previous
#include <cuda_runtime.h>
#include <cuda_bf16.h>
#include <cstdint>

// VQ nearest-code lookup via mma.sync bf16 6-pass fp32 emulation.
// x:   [32, 64, 64, 64] fp32 -> row r = b*4096 + n; elem (r,c) at x[b*262144 + c*4096 + n]
// emb: [512, 64] fp32
// out: flat [131072, 64] fp32 row-major.

#define THREADS  256
#define NTILES   1024          // 131072 rows / 128 rows per tile
#define GRIDSZ   148
#define B_TERM   65536         // one bf16 codebook term: 512 rows x 128B
#define SM_ESQ   (3 * B_TERM)
#define SMEM_TOTAL (3 * B_TERM + 2048)
#define GAP_THRESH 2.5e-4f

__device__ __forceinline__ uint32_t smem_u32(const void* p) {
    uint32_t a;
    asm("{ .reg .u64 t; cvta.to.shared.u64 t, %1; cvt.u32.u64 %0, t; }" : "=r"(a) : "l"(p));
    return a;
}

__device__ __forceinline__ void mma16816(float& d0, float& d1, float& d2, float& d3,
                                         uint32_t a0, uint32_t a1, uint32_t a2, uint32_t a3,
                                         uint32_t b0, uint32_t b1) {
    asm("mma.sync.aligned.m16n8k16.row.col.f32.bf16.bf16.f32 "
        "{%0,%1,%2,%3}, {%4,%5,%6,%7}, {%8,%9}, {%0,%1,%2,%3};"
        : "+f"(d0), "+f"(d1), "+f"(d2), "+f"(d3)
        : "r"(a0), "r"(a1), "r"(a2), "r"(a3), "r"(b0), "r"(b1));
}

__device__ __forceinline__ void ldm4(uint32_t& r0, uint32_t& r1, uint32_t& r2, uint32_t& r3,
                                     uint32_t addr) {
    asm volatile("ldmatrix.sync.aligned.m8n8.x4.shared.b16 {%0,%1,%2,%3}, [%4];"
                 : "=r"(r0), "=r"(r1), "=r"(r2), "=r"(r3) : "r"(addr));
}

// Exact 3-term bf16 split (round-and-subtract residuals are exact in fp32).
__device__ __forceinline__ void split3(float v, uint16_t& h, uint16_t& m, uint16_t& l) {
    __nv_bfloat16 bh = __float2bfloat16_rn(v);
    float r1 = v - __bfloat162float(bh);
    __nv_bfloat16 bm = __float2bfloat16_rn(r1);
    float r2 = r1 - __bfloat162float(bm);
    __nv_bfloat16 bl = __float2bfloat16_rn(r2);
    h = __bfloat16_as_ushort(bh); m = __bfloat16_as_ushort(bm); l = __bfloat16_as_ushort(bl);
}

// Streaming top-2 update (ascending n order; strict '<' keeps first index).
#define UPD(m_, n_, B1_, I1_, B2_, I2_) do {                        \
    bool _l1 = (m_) < (B1_);                                        \
    bool _l2 = (m_) < (B2_);                                        \
    B2_ = _l1 ? (B1_) : (_l2 ? (m_) : (B2_));                       \
    I2_ = _l1 ? (I1_) : (_l2 ? (n_) : (I2_));                       \
    B1_ = _l1 ? (m_) : (B1_);                                       \
    I1_ = _l1 ? (n_) : (I1_);                                       \
} while (0)

// Merge top-2 across lane ^off (exact top-2 of union, index tie -> smaller).
#define MRG(off, B1_, I1_, B2_, I2_) do {                                        \
    float _ob1 = __shfl_xor_sync(0xffffffffu, B1_, off);                         \
    int   _oi1 = __shfl_xor_sync(0xffffffffu, I1_, off);                         \
    float _ob2 = __shfl_xor_sync(0xffffffffu, B2_, off);                         \
    int   _oi2 = __shfl_xor_sync(0xffffffffu, I2_, off);                         \
    bool _c = (_ob1 < (B1_)) || (_ob1 == (B1_) && _oi1 < (I1_));                 \
    float _lb = _c ? (B1_) : _ob1; int _li = _c ? (I1_) : _oi1;                  \
    float _sb = _c ? _ob2 : (B2_); int _si = _c ? _oi2 : (I2_);                  \
    bool _s = (_lb < _sb) || (_lb == _sb && _li < _si);                          \
    B1_ = _c ? _ob1 : (B1_); I1_ = _c ? _oi1 : (I1_);                            \
    B2_ = _s ? _lb : _sb;    I2_ = _s ? _li : _si;                               \
} while (0)

__global__ void __launch_bounds__(THREADS, 1)
vq_mma_kernel(const float* __restrict__ x, const float* __restrict__ emb,
              float* __restrict__ out)
{
    extern __shared__ char sm[];
    float* esq = (float*)(sm + SM_ESQ);
    const float2* esq2 = (const float2*)esq;
    const uint32_t sbase = smem_u32(sm);

    const int tid  = threadIdx.x;
    const int w    = tid >> 5;
    const int lane = tid & 31;
    const int g    = lane >> 2;     // mma group id (row within 8)
    const int tig  = lane & 3;      // thread in group

    // ---- Stage codebook: 3 bf16 terms, ldmatrix-friendly XOR swizzle ----
    // term layout: row n (128B), 16B-unit u stored at (u ^ (n&7)).
    for (int idx = tid; idx < 512 * 64; idx += THREADS) {
        const int n = idx >> 6, k = idx & 63;
        uint16_t h, m, l;
        split3(__ldg(&emb[idx]), h, m, l);
        const uint32_t o = (uint32_t)(n * 128 + ((((k >> 3) ^ (n & 7))) << 4) + ((k & 7) << 1));
        *(uint16_t*)(sm + o)              = h;
        *(uint16_t*)(sm + B_TERM + o)     = m;
        *(uint16_t*)(sm + 2 * B_TERM + o) = l;
    }
    for (int n = tid; n < 512; n += THREADS) {
        float s = 0.0f;
        #pragma unroll
        for (int k = 0; k < 64; k++) { float v = __ldg(&emb[n * 64 + k]); s = fmaf(v, v, s); }
        esq[n] = s;
    }
    __syncthreads();

    // ldmatrix per-thread base addresses: term t, k-pair p.
    const int l7 = lane & 7, sel = lane >> 3;
    uint32_t lmb[3][2];
    #pragma unroll
    for (int t = 0; t < 3; t++)
        #pragma unroll
        for (int p = 0; p < 2; p++)
            lmb[t][p] = sbase + t * B_TERM + l7 * 128 + (((4 * p + sel) ^ l7) << 4);

    const float2* e2p = (const float2*)emb;
    float2* o2 = (float2*)out;

    for (int tile = blockIdx.x; tile < NTILES; tile += GRIDSZ) {
        const int rlo = tile * 128 + w * 16 + g;        // frag rows: rlo, rlo+8
        const int b   = rlo >> 12;
        const int nlo = rlo & 4095;
        const float* xb = x + (size_t)b * 262144;

        // x values this thread owns: rows g/g+8, cols {2tig,2tig+1,2tig+8,2tig+9}+16ks
        float xg[16], xh[16];
        #pragma unroll
        for (int ks = 0; ks < 4; ks++)
            #pragma unroll
            for (int j = 0; j < 4; j++) {
                const int c = ks * 16 + tig * 2 + (j & 1) + ((j >> 1) << 3);
                xg[ks * 4 + j] = __ldg(&xb[(size_t)c * 4096 + nlo]);
                xh[ks * 4 + j] = __ldg(&xb[(size_t)c * 4096 + nlo + 8]);
            }

        // Build A fragments (3 terms x 4 ksteps x 4 regs).
        uint32_t A1[16], A2[16], A3[16];
        #pragma unroll
        for (int ks = 0; ks < 4; ks++) {
            uint16_t h0, m0, l0, h1, m1, l1;
            // reg0: row g, cols 2tig,2tig+1
            split3(xg[ks*4+0], h0, m0, l0); split3(xg[ks*4+1], h1, m1, l1);
            A1[ks*4+0] = (uint32_t)h0 | ((uint32_t)h1 << 16);
            A2[ks*4+0] = (uint32_t)m0 | ((uint32_t)m1 << 16);
            A3[ks*4+0] = (uint32_t)l0 | ((uint32_t)l1 << 16);
            // reg1: row g+8, cols 2tig,2tig+1
            split3(xh[ks*4+0], h0, m0, l0); split3(xh[ks*4+1], h1, m1, l1);
            A1[ks*4+1] = (uint32_t)h0 | ((uint32_t)h1 << 16);
            A2[ks*4+1] = (uint32_t)m0 | ((uint32_t)m1 << 16);
            A3[ks*4+1] = (uint32_t)l0 | ((uint32_t)l1 << 16);
            // reg2: row g, cols 2tig+8,2tig+9
            split3(xg[ks*4+2], h0, m0, l0); split3(xg[ks*4+3], h1, m1, l1);
            A1[ks*4+2] = (uint32_t)h0 | ((uint32_t)h1 << 16);
            A2[ks*4+2] = (uint32_t)m0 | ((uint32_t)m1 << 16);
            A3[ks*4+2] = (uint32_t)l0 | ((uint32_t)l1 << 16);
            // reg3: row g+8, cols 2tig+8,2tig+9
            split3(xh[ks*4+2], h0, m0, l0); split3(xh[ks*4+3], h1, m1, l1);
            A1[ks*4+3] = (uint32_t)h0 | ((uint32_t)h1 << 16);
            A2[ks*4+3] = (uint32_t)m0 | ((uint32_t)m1 << 16);
            A3[ks*4+3] = (uint32_t)l0 | ((uint32_t)l1 << 16);
        }

        float b1l = 3.402823466e38f, b2l = 3.402823466e38f;
        float b1h = 3.402823466e38f, b2h = 3.402823466e38f;
        int   i1l = 0, i2l = 0, i1h = 0, i2h = 0;

        #pragma unroll 1
        for (int nc = 0; nc < 64; nc++) {
            const uint32_t co = (uint32_t)nc << 10;
            uint32_t B1f[8], B2f[8], B3f[8];
            ldm4(B1f[0], B1f[1], B1f[2], B1f[3], lmb[0][0] + co);
            ldm4(B1f[4], B1f[5], B1f[6], B1f[7], lmb[0][1] + co);
            ldm4(B2f[0], B2f[1], B2f[2], B2f[3], lmb[1][0] + co);
            ldm4(B2f[4], B2f[5], B2f[6], B2f[7], lmb[1][1] + co);
            ldm4(B3f[0], B3f[1], B3f[2], B3f[3], lmb[2][0] + co);
            ldm4(B3f[4], B3f[5], B3f[6], B3f[7], lmb[2][1] + co);

            float DB0 = 0, DB1 = 0, DB2 = 0, DB3 = 0;      // pass (1,1)
            float DS0 = 0, DS1 = 0, DS2 = 0, DS3 = 0;      // 5 small passes
            #pragma unroll
            for (int ks = 0; ks < 4; ks++) {
                const uint32_t b1a = B1f[2*ks], b1b = B1f[2*ks+1];
                const uint32_t b2a = B2f[2*ks], b2b = B2f[2*ks+1];
                const uint32_t b3a = B3f[2*ks], b3b = B3f[2*ks+1];
                // smallest-magnitude first within the small accumulator
                mma16816(DS0,DS1,DS2,DS3, A3[4*ks],A3[4*ks+1],A3[4*ks+2],A3[4*ks+3], b1a,b1b);
                mma16816(DS0,DS1,DS2,DS3, A1[4*ks],A1[4*ks+1],A1[4*ks+2],A1[4*ks+3], b3a,b3b);
                mma16816(DS0,DS1,DS2,DS3, A2[4*ks],A2[4*ks+1],A2[4*ks+2],A2[4*ks+3], b2a,b2b);
                mma16816(DS0,DS1,DS2,DS3, A2[4*ks],A2[4*ks+1],A2[4*ks+2],A2[4*ks+3], b1a,b1b);
                mma16816(DS0,DS1,DS2,DS3, A1[4*ks],A1[4*ks+1],A1[4*ks+2],A1[4*ks+3], b2a,b2b);
                mma16816(DB0,DB1,DB2,DB3, A1[4*ks],A1[4*ks+1],A1[4*ks+2],A1[4*ks+3], b1a,b1b);
            }

            const float2 sv = esq2[nc * 4 + tig];
            const int n0 = nc * 8 + 2 * tig;
            float m0 = fmaf(-2.0f, DB0 + DS0, sv.x);
            float m1 = fmaf(-2.0f, DB1 + DS1, sv.y);
            float m2 = fmaf(-2.0f, DB2 + DS2, sv.x);
            float m3 = fmaf(-2.0f, DB3 + DS3, sv.y);
            UPD(m0, n0,     b1l, i1l, b2l, i2l);
            UPD(m1, n0 + 1, b1l, i1l, b2l, i2l);
            UPD(m2, n0,     b1h, i1h, b2h, i2h);
            UPD(m3, n0 + 1, b1h, i1h, b2h, i2h);
        }

        // Exact top-2 across the 4 lanes of each group.
        MRG(1, b1l, i1l, b2l, i2l); MRG(2, b1l, i1l, b2l, i2l);
        MRG(1, b1h, i1h, b2h, i2h); MRG(2, b1h, i1h, b2h, i2h);

        // Ambiguity fallback: exact fp32 dot for top-2 candidates.
        const bool trl = (b2l - b1l) < GAP_THRESH;
        const bool trh = (b2h - b1h) < GAP_THRESH;
        if (__ballot_sync(0xffffffffu, trl || trh)) {
            // row lo
            {
                const int ca = i1l, cb = i2l;
                float c1 = 0.0f, c2 = 0.0f;
                #pragma unroll
                for (int ks = 0; ks < 4; ks++) {
                    float2 ea0 = __ldg(&e2p[ca * 32 + ks * 8 + tig]);
                    float2 ea1 = __ldg(&e2p[ca * 32 + ks * 8 + tig + 4]);
                    float2 eb0 = __ldg(&e2p[cb * 32 + ks * 8 + tig]);
                    float2 eb1 = __ldg(&e2p[cb * 32 + ks * 8 + tig + 4]);
                    c1 = fmaf(xg[ks*4+0], ea0.x, c1); c1 = fmaf(xg[ks*4+1], ea0.y, c1);
                    c1 = fmaf(xg[ks*4+2], ea1.x, c1); c1 = fmaf(xg[ks*4+3], ea1.y, c1);
                    c2 = fmaf(xg[ks*4+0], eb0.x, c2); c2 = fmaf(xg[ks*4+1], eb0.y, c2);
                    c2 = fmaf(xg[ks*4+2], eb1.x, c2); c2 = fmaf(xg[ks*4+3], eb1.y, c2);
                }
                c1 += __shfl_xor_sync(0xffffffffu, c1, 1); c1 += __shfl_xor_sync(0xffffffffu, c1, 2);
                c2 += __shfl_xor_sync(0xffffffffu, c2, 1); c2 += __shfl_xor_sync(0xffffffffu, c2, 2);
                const float dA = fmaf(-2.0f, c1, esq[ca]);
                const float dB = fmaf(-2.0f, c2, esq[cb]);
                if (trl && ((dB < dA) || (dB == dA && cb < ca))) i1l = cb;
            }
            // row hi
            {
                const int ca = i1h, cb = i2h;
                float c1 = 0.0f, c2 = 0.0f;
                #pragma unroll
                for (int ks = 0; ks < 4; ks++) {
                    float2 ea0 = __ldg(&e2p[ca * 32 + ks * 8 + tig]);
                    float2 ea1 = __ldg(&e2p[ca * 32 + ks * 8 + tig + 4]);
                    float2 eb0 = __ldg(&e2p[cb * 32 + ks * 8 + tig]);
                    float2 eb1 = __ldg(&e2p[cb * 32 + ks * 8 + tig + 4]);
                    c1 = fmaf(xh[ks*4+0], ea0.x, c1); c1 = fmaf(xh[ks*4+1], ea0.y, c1);
                    c1 = fmaf(xh[ks*4+2], ea1.x, c1); c1 = fmaf(xh[ks*4+3], ea1.y, c1);
                    c2 = fmaf(xh[ks*4+0], eb0.x, c2); c2 = fmaf(xh[ks*4+1], eb0.y, c2);
                    c2 = fmaf(xh[ks*4+2], eb1.x, c2); c2 = fmaf(xh[ks*4+3], eb1.y, c2);
                }
                c1 += __shfl_xor_sync(0xffffffffu, c1, 1); c1 += __shfl_xor_sync(0xffffffffu, c1, 2);
                c2 += __shfl_xor_sync(0xffffffffu, c2, 1); c2 += __shfl_xor_sync(0xffffffffu, c2, 2);
                const float dA = fmaf(-2.0f, c1, esq[ca]);
                const float dB = fmaf(-2.0f, c2, esq[cb]);
                if (trh && ((dB < dA) || (dB == dA && cb < ca))) i1h = cb;
            }
        }

        // Straight-through output: out = x + (e - x), exact fp32.
        {
            const size_t obl = (size_t)rlo * 32;
            const size_t obh = (size_t)(rlo + 8) * 32;
            #pragma unroll
            for (int ks = 0; ks < 4; ks++) {
                float2 e0 = __ldg(&e2p[i1l * 32 + ks * 8 + tig]);
                float2 e1 = __ldg(&e2p[i1l * 32 + ks * 8 + tig + 4]);
                float2 v;
                v.x = xg[ks*4+0] + (e0.x - xg[ks*4+0]);
                v.y = xg[ks*4+1] + (e0.y - xg[ks*4+1]);
                o2[obl + ks * 8 + tig] = v;
                v.x = xg[ks*4+2] + (e1.x - xg[ks*4+2]);
                v.y = xg[ks*4+3] + (e1.y - xg[ks*4+3]);
                o2[obl + ks * 8 + tig + 4] = v;

                e0 = __ldg(&e2p[i1h * 32 + ks * 8 + tig]);
                e1 = __ldg(&e2p[i1h * 32 + ks * 8 + tig + 4]);
                v.x = xh[ks*4+0] + (e0.x - xh[ks*4+0]);
                v.y = xh[ks*4+1] + (e0.y - xh[ks*4+1]);
                o2[obh + ks * 8 + tig] = v;
                v.x = xh[ks*4+2] + (e1.x - xh[ks*4+2]);
                v.y = xh[ks*4+3] + (e1.y - xh[ks*4+3]);
                o2[obh + ks * 8 + tig + 4] = v;
            }
        }
    }
}

extern "C" void kernel_launch(void* const* d_in, const int* in_sizes, int n_in,
                              void* d_out, int out_size)
{
    const float* x   = (const float*)d_in[0];
    const float* emb = (const float*)d_in[1];
    float* out = (float*)d_out;

    cudaFuncSetAttribute(vq_mma_kernel,
                         cudaFuncAttributeMaxDynamicSharedMemorySize, SMEM_TOTAL);
    vq_mma_kernel<<<GRIDSZ, THREADS, SMEM_TOTAL>>>(x, emb, out);
}

// round 9
// speedup vs baseline: 1.4316x; 1.2151x over previous
#include <cuda_runtime.h>
#include <cuda_bf16.h>
#include <cstdint>

// VQ nearest-code lookup via mma.sync bf16 4-pass fp32 emulation (2-term splits),
// top-3 tracking + exact fp32 recheck whenever the top-2 gap is ambiguous.
// x:   [32, 64, 64, 64] fp32 -> row r = b*4096 + n; elem (r,c) at x[b*262144 + c*4096 + n]
// emb: [512, 64] fp32
// out: flat [131072, 64] fp32 row-major.

#define THREADS  256
#define NTILES   1024          // 131072 rows / 128 rows per tile
#define GRIDSZ   148
#define B_TERM   65536         // one bf16 codebook term: 512 rows x 128B
#define SM_ESQ   (2 * B_TERM)
#define SMEM_TOTAL (2 * B_TERM + 2048)
// Hard bound on approx-distance error is ~5.4e-3 (coherent worst case).
// Threshold must exceed 2*E_max: 2e-2 gives ~2x margin on the hard bound.
#define GAP_THRESH 2.0e-2f

__device__ __forceinline__ uint32_t smem_u32(const void* p) {
    uint32_t a;
    asm("{ .reg .u64 t; cvta.to.shared.u64 t, %1; cvt.u32.u64 %0, t; }" : "=r"(a) : "l"(p));
    return a;
}

__device__ __forceinline__ void mma16816(float& d0, float& d1, float& d2, float& d3,
                                         uint32_t a0, uint32_t a1, uint32_t a2, uint32_t a3,
                                         uint32_t b0, uint32_t b1) {
    asm("mma.sync.aligned.m16n8k16.row.col.f32.bf16.bf16.f32 "
        "{%0,%1,%2,%3}, {%4,%5,%6,%7}, {%8,%9}, {%0,%1,%2,%3};"
        : "+f"(d0), "+f"(d1), "+f"(d2), "+f"(d3)
        : "r"(a0), "r"(a1), "r"(a2), "r"(a3), "r"(b0), "r"(b1));
}

__device__ __forceinline__ void ldm4(uint32_t& r0, uint32_t& r1, uint32_t& r2, uint32_t& r3,
                                     uint32_t addr) {
    asm volatile("ldmatrix.sync.aligned.m8n8.x4.shared.b16 {%0,%1,%2,%3}, [%4];"
                 : "=r"(r0), "=r"(r1), "=r"(r2), "=r"(r3) : "r"(addr));
}

// Exact 2-term bf16 split (round-and-subtract residual exact in fp32).
__device__ __forceinline__ void split2(float v, uint16_t& h, uint16_t& l) {
    __nv_bfloat16 bh = __float2bfloat16_rn(v);
    float r = v - __bfloat162float(bh);
    __nv_bfloat16 bl = __float2bfloat16_rn(r);
    h = __bfloat16_as_ushort(bh); l = __bfloat16_as_ushort(bl);
}

// Streaming top-3 insert (ascending n order; strict '<' keeps first index).
#define UPD3(m_, n_, B1_, I1_, B2_, I2_, B3_, I3_) do {                   \
    bool _l1 = (m_) < (B1_);                                              \
    bool _l2 = (m_) < (B2_);                                              \
    bool _l3 = (m_) < (B3_);                                              \
    B3_ = _l2 ? (B2_) : (_l3 ? (m_) : (B3_));                             \
    I3_ = _l2 ? (I2_) : (_l3 ? (n_) : (I3_));                             \
    B2_ = _l1 ? (B1_) : (_l2 ? (m_) : (B2_));                             \
    I2_ = _l1 ? (I1_) : (_l2 ? (n_) : (I2_));                             \
    B1_ = _l1 ? (m_) : (B1_);                                             \
    I1_ = _l1 ? (n_) : (I1_);                                             \
} while (0)

// Lexicographic insert (tie -> smaller index), used for cross-lane merges.
#define INS3(m_, n_, B1_, I1_, B2_, I2_, B3_, I3_) do {                   \
    bool _l1 = ((m_) < (B1_)) || ((m_) == (B1_) && (n_) < (I1_));         \
    bool _l2 = ((m_) < (B2_)) || ((m_) == (B2_) && (n_) < (I2_));         \
    bool _l3 = ((m_) < (B3_)) || ((m_) == (B3_) && (n_) < (I3_));         \
    B3_ = _l2 ? (B2_) : (_l3 ? (m_) : (B3_));                             \
    I3_ = _l2 ? (I2_) : (_l3 ? (n_) : (I3_));                             \
    B2_ = _l1 ? (B1_) : (_l2 ? (m_) : (B2_));                             \
    I2_ = _l1 ? (I1_) : (_l2 ? (n_) : (I2_));                             \
    B1_ = _l1 ? (m_) : (B1_);                                             \
    I1_ = _l1 ? (n_) : (I1_);                                             \
} while (0)

// Merge top-3 across lane ^off: insert other lane's sorted entries.
#define MRG3(off, B1_, I1_, B2_, I2_, B3_, I3_) do {                      \
    float _o1 = __shfl_xor_sync(0xffffffffu, B1_, off);                   \
    int   _j1 = __shfl_xor_sync(0xffffffffu, I1_, off);                   \
    float _o2 = __shfl_xor_sync(0xffffffffu, B2_, off);                   \
    int   _j2 = __shfl_xor_sync(0xffffffffu, I2_, off);                   \
    float _o3 = __shfl_xor_sync(0xffffffffu, B3_, off);                   \
    int   _j3 = __shfl_xor_sync(0xffffffffu, I3_, off);                   \
    INS3(_o1, _j1, B1_, I1_, B2_, I2_, B3_, I3_);                         \
    INS3(_o2, _j2, B1_, I1_, B2_, I2_, B3_, I3_);                         \
    INS3(_o3, _j3, B1_, I1_, B2_, I2_, B3_, I3_);                         \
} while (0)

// Exact fp32 dot of row (xr, 16 vals, mma layout) with code c; quad-reduced.
__device__ __forceinline__ float exact_dot(const float2* __restrict__ e2p,
                                           int c, const float* xr, int tig) {
    float s = 0.0f;
    #pragma unroll
    for (int ks = 0; ks < 4; ks++) {
        float2 e0 = __ldg(&e2p[c * 32 + ks * 8 + tig]);
        float2 e1 = __ldg(&e2p[c * 32 + ks * 8 + tig + 4]);
        s = fmaf(xr[ks*4+0], e0.x, s); s = fmaf(xr[ks*4+1], e0.y, s);
        s = fmaf(xr[ks*4+2], e1.x, s); s = fmaf(xr[ks*4+3], e1.y, s);
    }
    s += __shfl_xor_sync(0xffffffffu, s, 1);
    s += __shfl_xor_sync(0xffffffffu, s, 2);
    return s;
}

__global__ void __launch_bounds__(THREADS, 1)
vq_mma_kernel(const float* __restrict__ x, const float* __restrict__ emb,
              float* __restrict__ out)
{
    extern __shared__ char sm[];
    float* esq = (float*)(sm + SM_ESQ);
    const float2* esq2 = (const float2*)esq;
    const uint32_t sbase = smem_u32(sm);

    const int tid  = threadIdx.x;
    const int w    = tid >> 5;
    const int lane = tid & 31;
    const int g    = lane >> 2;     // row within 8
    const int tig  = lane & 3;      // thread in group

    // ---- Stage codebook: 2 bf16 terms, ldmatrix XOR swizzle ----
    for (int idx = tid; idx < 512 * 64; idx += THREADS) {
        const int n = idx >> 6, k = idx & 63;
        uint16_t h, l;
        split2(__ldg(&emb[idx]), h, l);
        const uint32_t o = (uint32_t)(n * 128 + ((((k >> 3) ^ (n & 7))) << 4) + ((k & 7) << 1));
        *(uint16_t*)(sm + o)          = h;
        *(uint16_t*)(sm + B_TERM + o) = l;
    }
    for (int n = tid; n < 512; n += THREADS) {
        float s = 0.0f;
        #pragma unroll
        for (int k = 0; k < 64; k++) { float v = __ldg(&emb[n * 64 + k]); s = fmaf(v, v, s); }
        esq[n] = s;
    }
    __syncthreads();

    // ldmatrix base addresses: term t, k-pair p.
    const int l7 = lane & 7, sel = lane >> 3;
    uint32_t lmb[2][2];
    #pragma unroll
    for (int t = 0; t < 2; t++)
        #pragma unroll
        for (int p = 0; p < 2; p++)
            lmb[t][p] = sbase + t * B_TERM + l7 * 128 + (((4 * p + sel) ^ l7) << 4);

    const float2* e2p = (const float2*)emb;
    float2* o2 = (float2*)out;

    for (int tile = blockIdx.x; tile < NTILES; tile += GRIDSZ) {
        const int rlo = tile * 128 + w * 16 + g;        // frag rows: rlo, rlo+8
        const int b   = rlo >> 12;
        const int nlo = rlo & 4095;
        const float* xb = x + (size_t)b * 262144;

        // x values this thread owns (mma A layout).
        float xg[16], xh[16];
        #pragma unroll
        for (int ks = 0; ks < 4; ks++)
            #pragma unroll
            for (int j = 0; j < 4; j++) {
                const int c = ks * 16 + tig * 2 + (j & 1) + ((j >> 1) << 3);
                xg[ks * 4 + j] = __ldg(&xb[(size_t)c * 4096 + nlo]);
                xh[ks * 4 + j] = __ldg(&xb[(size_t)c * 4096 + nlo + 8]);
            }

        // A fragments: 2 terms x 4 ksteps x 4 regs.
        uint32_t A1[16], A2[16];
        #pragma unroll
        for (int ks = 0; ks < 4; ks++) {
            uint16_t h0, l0, h1, l1;
            split2(xg[ks*4+0], h0, l0); split2(xg[ks*4+1], h1, l1);
            A1[ks*4+0] = (uint32_t)h0 | ((uint32_t)h1 << 16);
            A2[ks*4+0] = (uint32_t)l0 | ((uint32_t)l1 << 16);
            split2(xh[ks*4+0], h0, l0); split2(xh[ks*4+1], h1, l1);
            A1[ks*4+1] = (uint32_t)h0 | ((uint32_t)h1 << 16);
            A2[ks*4+1] = (uint32_t)l0 | ((uint32_t)l1 << 16);
            split2(xg[ks*4+2], h0, l0); split2(xg[ks*4+3], h1, l1);
            A1[ks*4+2] = (uint32_t)h0 | ((uint32_t)h1 << 16);
            A2[ks*4+2] = (uint32_t)l0 | ((uint32_t)l1 << 16);
            split2(xh[ks*4+2], h0, l0); split2(xh[ks*4+3], h1, l1);
            A1[ks*4+3] = (uint32_t)h0 | ((uint32_t)h1 << 16);
            A2[ks*4+3] = (uint32_t)l0 | ((uint32_t)l1 << 16);
        }

        float b1l = 3.402823466e38f, b2l = 3.402823466e38f, b3l = 3.402823466e38f;
        float b1h = 3.402823466e38f, b2h = 3.402823466e38f, b3h = 3.402823466e38f;
        int   i1l = 0, i2l = 0, i3l = 0, i1h = 0, i2h = 0, i3h = 0;

        // Two 8-code streams per iteration; 32 MMAs across 4 accumulator chains.
        #pragma unroll 1
        for (int nc = 0; nc < 64; nc += 2) {
            const uint32_t coA = (uint32_t)nc << 10;
            const uint32_t coB = coA + 1024;
            uint32_t BhA[8], BlA[8], BhB[8], BlB[8];
            ldm4(BhA[0], BhA[1], BhA[2], BhA[3], lmb[0][0] + coA);
            ldm4(BhA[4], BhA[5], BhA[6], BhA[7], lmb[0][1] + coA);
            ldm4(BlA[0], BlA[1], BlA[2], BlA[3], lmb[1][0] + coA);
            ldm4(BlA[4], BlA[5], BlA[6], BlA[7], lmb[1][1] + coA);
            ldm4(BhB[0], BhB[1], BhB[2], BhB[3], lmb[0][0] + coB);
            ldm4(BhB[4], BhB[5], BhB[6], BhB[7], lmb[0][1] + coB);
            ldm4(BlB[0], BlB[1], BlB[2], BlB[3], lmb[1][0] + coB);
            ldm4(BlB[4], BlB[5], BlB[6], BlB[7], lmb[1][1] + coB);

            float DBa0=0,DBa1=0,DBa2=0,DBa3=0, DSa0=0,DSa1=0,DSa2=0,DSa3=0;
            float DBb0=0,DBb1=0,DBb2=0,DBb3=0, DSb0=0,DSb1=0,DSb2=0,DSb3=0;
            #pragma unroll
            for (int ks = 0; ks < 4; ks++) {
                const uint32_t a10=A1[4*ks], a11=A1[4*ks+1], a12=A1[4*ks+2], a13=A1[4*ks+3];
                const uint32_t a20=A2[4*ks], a21=A2[4*ks+1], a22=A2[4*ks+2], a23=A2[4*ks+3];
                // smallest-magnitude first within each DS chain; a/b interleaved
                mma16816(DSa0,DSa1,DSa2,DSa3, a20,a21,a22,a23, BlA[2*ks],BlA[2*ks+1]); // (2,2)
                mma16816(DSb0,DSb1,DSb2,DSb3, a20,a21,a22,a23, BlB[2*ks],BlB[2*ks+1]);
                mma16816(DSa0,DSa1,DSa2,DSa3, a20,a21,a22,a23, BhA[2*ks],BhA[2*ks+1]); // (2,1)
                mma16816(DSb0,DSb1,DSb2,DSb3, a20,a21,a22,a23, BhB[2*ks],BhB[2*ks+1]);
                mma16816(DSa0,DSa1,DSa2,DSa3, a10,a11,a12,a13, BlA[2*ks],BlA[2*ks+1]); // (1,2)
                mma16816(DSb0,DSb1,DSb2,DSb3, a10,a11,a12,a13, BlB[2*ks],BlB[2*ks+1]);
                mma16816(DBa0,DBa1,DBa2,DBa3, a10,a11,a12,a13, BhA[2*ks],BhA[2*ks+1]); // (1,1)
                mma16816(DBb0,DBb1,DBb2,DBb3, a10,a11,a12,a13, BhB[2*ks],BhB[2*ks+1]);
            }

            {
                const float2 sv = esq2[nc * 4 + tig];
                const int n0 = nc * 8 + 2 * tig;
                float m0 = fmaf(-2.0f, DBa0 + DSa0, sv.x);
                float m1 = fmaf(-2.0f, DBa1 + DSa1, sv.y);
                float m2 = fmaf(-2.0f, DBa2 + DSa2, sv.x);
                float m3 = fmaf(-2.0f, DBa3 + DSa3, sv.y);
                UPD3(m0, n0,     b1l, i1l, b2l, i2l, b3l, i3l);
                UPD3(m1, n0 + 1, b1l, i1l, b2l, i2l, b3l, i3l);
                UPD3(m2, n0,     b1h, i1h, b2h, i2h, b3h, i3h);
                UPD3(m3, n0 + 1, b1h, i1h, b2h, i2h, b3h, i3h);
            }
            {
                const float2 sv = esq2[(nc + 1) * 4 + tig];
                const int n0 = (nc + 1) * 8 + 2 * tig;
                float m0 = fmaf(-2.0f, DBb0 + DSb0, sv.x);
                float m1 = fmaf(-2.0f, DBb1 + DSb1, sv.y);
                float m2 = fmaf(-2.0f, DBb2 + DSb2, sv.x);
                float m3 = fmaf(-2.0f, DBb3 + DSb3, sv.y);
                UPD3(m0, n0,     b1l, i1l, b2l, i2l, b3l, i3l);
                UPD3(m1, n0 + 1, b1l, i1l, b2l, i2l, b3l, i3l);
                UPD3(m2, n0,     b1h, i1h, b2h, i2h, b3h, i3h);
                UPD3(m3, n0 + 1, b1h, i1h, b2h, i2h, b3h, i3h);
            }
        }

        // Exact top-3 across the 4 lanes of each group (all lanes converge).
        MRG3(1, b1l, i1l, b2l, i2l, b3l, i3l); MRG3(2, b1l, i1l, b2l, i2l, b3l, i3l);
        MRG3(1, b1h, i1h, b2h, i2h, b3h, i3h); MRG3(2, b1h, i1h, b2h, i2h, b3h, i3h);

        // Ambiguity fallback: if the top-2 gap is below threshold, re-rank the
        // top-3 candidates with exact fp32 distances. (Any case where the true
        // argmin could sit outside top-1 implies b2-b1 < 2*E_max << GAP_THRESH.)
        const bool trl = (b2l - b1l) < GAP_THRESH;
        const bool trh = (b2h - b1h) < GAP_THRESH;
        if (__ballot_sync(0xffffffffu, trl || trh)) {
            {
                const float dA = fmaf(-2.0f, exact_dot(e2p, i1l, xg, tig), esq[i1l]);
                const float dB = fmaf(-2.0f, exact_dot(e2p, i2l, xg, tig), esq[i2l]);
                const float dC = fmaf(-2.0f, exact_dot(e2p, i3l, xg, tig), esq[i3l]);
                int   bi = i1l; float bd = dA;
                if ((dB < bd) || (dB == bd && i2l < bi)) { bd = dB; bi = i2l; }
                if ((dC < bd) || (dC == bd && i3l < bi)) { bd = dC; bi = i3l; }
                if (trl) i1l = bi;
            }
            {
                const float dA = fmaf(-2.0f, exact_dot(e2p, i1h, xh, tig), esq[i1h]);
                const float dB = fmaf(-2.0f, exact_dot(e2p, i2h, xh, tig), esq[i2h]);
                const float dC = fmaf(-2.0f, exact_dot(e2p, i3h, xh, tig), esq[i3h]);
                int   bi = i1h; float bd = dA;
                if ((dB < bd) || (dB == bd && i2h < bi)) { bd = dB; bi = i2h; }
                if ((dC < bd) || (dC == bd && i3h < bi)) { bd = dC; bi = i3h; }
                if (trh) i1h = bi;
            }
        }

        // Straight-through output: out = x + (e - x), fp32.
        {
            const size_t obl = (size_t)rlo * 32;
            const size_t obh = (size_t)(rlo + 8) * 32;
            #pragma unroll
            for (int ks = 0; ks < 4; ks++) {
                float2 e0 = __ldg(&e2p[i1l * 32 + ks * 8 + tig]);
                float2 e1 = __ldg(&e2p[i1l * 32 + ks * 8 + tig + 4]);
                float2 v;
                v.x = xg[ks*4+0] + (e0.x - xg[ks*4+0]);
                v.y = xg[ks*4+1] + (e0.y - xg[ks*4+1]);
                o2[obl + ks * 8 + tig] = v;
                v.x = xg[ks*4+2] + (e1.x - xg[ks*4+2]);
                v.y = xg[ks*4+3] + (e1.y - xg[ks*4+3]);
                o2[obl + ks * 8 + tig + 4] = v;

                e0 = __ldg(&e2p[i1h * 32 + ks * 8 + tig]);
                e1 = __ldg(&e2p[i1h * 32 + ks * 8 + tig + 4]);
                v.x = xh[ks*4+0] + (e0.x - xh[ks*4+0]);
                v.y = xh[ks*4+1] + (e0.y - xh[ks*4+1]);
                o2[obh + ks * 8 + tig] = v;
                v.x = xh[ks*4+2] + (e1.x - xh[ks*4+2]);
                v.y = xh[ks*4+3] + (e1.y - xh[ks*4+3]);
                o2[obh + ks * 8 + tig + 4] = v;
            }
        }
    }
}

extern "C" void kernel_launch(void* const* d_in, const int* in_sizes, int n_in,
                              void* d_out, int out_size)
{
    const float* x   = (const float*)d_in[0];
    const float* emb = (const float*)d_in[1];
    float* out = (float*)d_out;

    cudaFuncSetAttribute(vq_mma_kernel,
                         cudaFuncAttributeMaxDynamicSharedMemorySize, SMEM_TOTAL);
    vq_mma_kernel<<<GRIDSZ, THREADS, SMEM_TOTAL>>>(x, emb, out);
}

// round 10
// speedup vs baseline: 1.8026x; 1.2591x over previous
#include <cuda_runtime.h>
#include <cuda_bf16.h>
#include <cstdint>

// VQ nearest-code lookup via mma.sync bf16 4-pass fp32 emulation (2-term splits).
// Packed-key (IMNMX) top-3 tracking + exact fp32 recheck on ambiguous gaps.
// x:   [32, 64, 64, 64] fp32 -> row r = b*4096 + n; elem (r,c) at x[b*262144 + c*4096 + n]
// emb: [512, 64] fp32
// out: flat [131072, 64] fp32 row-major.

#define THREADS  384
#define NCHUNKS  8192          // 131072 rows / 16 rows per warp-chunk
#define GRIDSZ   148
#define NWARPS_T (GRIDSZ * (THREADS / 32))
#define B_TERM   65536         // one bf16 codebook term: 512 rows x 128B
#define SM_ESQ   (2 * B_TERM)
#define SMEM_TOTAL (2 * B_TERM + 2048)
#define BIAS     256.0f
// E_max ~ 5.4e-3 (emulation, coherent worst case) + 3.9e-3 (key truncation).
// Threshold must exceed 2*E_max; 3e-2 gives ~1.6x margin.
#define GAP_THRESH 3.0e-2f

__device__ __forceinline__ uint32_t smem_u32(const void* p) {
    uint32_t a;
    asm("{ .reg .u64 t; cvta.to.shared.u64 t, %1; cvt.u32.u64 %0, t; }" : "=r"(a) : "l"(p));
    return a;
}

__device__ __forceinline__ void mma16816(float& d0, float& d1, float& d2, float& d3,
                                         uint32_t a0, uint32_t a1, uint32_t a2, uint32_t a3,
                                         uint32_t b0, uint32_t b1) {
    asm("mma.sync.aligned.m16n8k16.row.col.f32.bf16.bf16.f32 "
        "{%0,%1,%2,%3}, {%4,%5,%6,%7}, {%8,%9}, {%0,%1,%2,%3};"
        : "+f"(d0), "+f"(d1), "+f"(d2), "+f"(d3)
        : "r"(a0), "r"(a1), "r"(a2), "r"(a3), "r"(b0), "r"(b1));
}

__device__ __forceinline__ void ldm4(uint32_t& r0, uint32_t& r1, uint32_t& r2, uint32_t& r3,
                                     uint32_t addr) {
    asm volatile("ldmatrix.sync.aligned.m8n8.x4.shared.b16 {%0,%1,%2,%3}, [%4];"
                 : "=r"(r0), "=r"(r1), "=r"(r2), "=r"(r3) : "r"(addr));
}

// Exact 2-term bf16 split (round-and-subtract residual exact in fp32).
__device__ __forceinline__ void split2(float v, uint16_t& h, uint16_t& l) {
    __nv_bfloat16 bh = __float2bfloat16_rn(v);
    float r = v - __bfloat162float(bh);
    __nv_bfloat16 bl = __float2bfloat16_rn(r);
    h = __bfloat16_as_ushort(bh); l = __bfloat16_as_ushort(bl);
}

// Packed-key top-3 insert: pure min/max sorting network (keeps B1<=B2<=B3).
// Keys are positive-float bit patterns (sign bit 0) -> unsigned order == float order.
#define INSK(k_, B1_, B2_, B3_) do {                          \
    uint32_t _t1 = max((B1_), (k_)); B1_ = min((B1_), (k_));  \
    uint32_t _t2 = max((B2_), _t1);  B2_ = min((B2_), _t1);   \
    B3_ = min((B3_), _t2);                                    \
} while (0)

// Lexicographic insert (tie -> smaller index), for cross-lane merges.
#define INS3(m_, n_, B1_, I1_, B2_, I2_, B3_, I3_) do {                   \
    bool _l1 = ((m_) < (B1_)) || ((m_) == (B1_) && (n_) < (I1_));         \
    bool _l2 = ((m_) < (B2_)) || ((m_) == (B2_) && (n_) < (I2_));         \
    bool _l3 = ((m_) < (B3_)) || ((m_) == (B3_) && (n_) < (I3_));         \
    B3_ = _l2 ? (B2_) : (_l3 ? (m_) : (B3_));                             \
    I3_ = _l2 ? (I2_) : (_l3 ? (n_) : (I3_));                             \
    B2_ = _l1 ? (B1_) : (_l2 ? (m_) : (B2_));                             \
    I2_ = _l1 ? (I1_) : (_l2 ? (n_) : (I2_));                             \
    B1_ = _l1 ? (m_) : (B1_);                                             \
    I1_ = _l1 ? (n_) : (I1_);                                             \
} while (0)

#define MRG3(off, B1_, I1_, B2_, I2_, B3_, I3_) do {                      \
    float _o1 = __shfl_xor_sync(0xffffffffu, B1_, off);                   \
    int   _j1 = __shfl_xor_sync(0xffffffffu, I1_, off);                   \
    float _o2 = __shfl_xor_sync(0xffffffffu, B2_, off);                   \
    int   _j2 = __shfl_xor_sync(0xffffffffu, I2_, off);                   \
    float _o3 = __shfl_xor_sync(0xffffffffu, B3_, off);                   \
    int   _j3 = __shfl_xor_sync(0xffffffffu, I3_, off);                   \
    INS3(_o1, _j1, B1_, I1_, B2_, I2_, B3_, I3_);                         \
    INS3(_o2, _j2, B1_, I1_, B2_, I2_, B3_, I3_);                         \
    INS3(_o3, _j3, B1_, I1_, B2_, I2_, B3_, I3_);                         \
} while (0)

// Exact fp32 dot of row (xr, 16 vals, mma layout) with code c; quad-reduced.
__device__ __forceinline__ float exact_dot(const float2* __restrict__ e2p,
                                           int c, const float* xr, int tig) {
    float s = 0.0f;
    #pragma unroll
    for (int ks = 0; ks < 4; ks++) {
        float2 e0 = __ldg(&e2p[c * 32 + ks * 8 + tig]);
        float2 e1 = __ldg(&e2p[c * 32 + ks * 8 + tig + 4]);
        s = fmaf(xr[ks*4+0], e0.x, s); s = fmaf(xr[ks*4+1], e0.y, s);
        s = fmaf(xr[ks*4+2], e1.x, s); s = fmaf(xr[ks*4+3], e1.y, s);
    }
    s += __shfl_xor_sync(0xffffffffu, s, 1);
    s += __shfl_xor_sync(0xffffffffu, s, 2);
    return s;
}

// Unpack a packed key: biased truncated value + global code index.
__device__ __forceinline__ void unpack_key(uint32_t key, int tig, float& v, int& n) {
    v = __uint_as_float(key & 0xFFFFFF80u);
    const int l = key & 127;
    n = (l >> 1) * 8 + 2 * tig + (l & 1);
}

__global__ void __launch_bounds__(THREADS, 1)
vq_mma_kernel(const float* __restrict__ x, const float* __restrict__ emb,
              float* __restrict__ out)
{
    extern __shared__ char sm[];
    float* esqb = (float*)(sm + SM_ESQ);      // e_sq + BIAS
    const float2* esqb2 = (const float2*)esqb;
    const uint32_t sbase = smem_u32(sm);

    const int tid  = threadIdx.x;
    const int w    = tid >> 5;
    const int lane = tid & 31;
    const int g    = lane >> 2;     // row within 8
    const int tig  = lane & 3;      // thread in group

    // ---- Stage codebook: 2 bf16 terms, ldmatrix XOR swizzle ----
    for (int idx = tid; idx < 512 * 64; idx += THREADS) {
        const int n = idx >> 6, k = idx & 63;
        uint16_t h, l;
        split2(__ldg(&emb[idx]), h, l);
        const uint32_t o = (uint32_t)(n * 128 + ((((k >> 3) ^ (n & 7))) << 4) + ((k & 7) << 1));
        *(uint16_t*)(sm + o)          = h;
        *(uint16_t*)(sm + B_TERM + o) = l;
    }
    for (int n = tid; n < 512; n += THREADS) {
        float s = 0.0f;
        #pragma unroll
        for (int k = 0; k < 64; k++) { float v = __ldg(&emb[n * 64 + k]); s = fmaf(v, v, s); }
        esqb[n] = s + BIAS;
    }
    __syncthreads();

    // ldmatrix base addresses: term t, k-pair p.
    const int l7 = lane & 7, sel = lane >> 3;
    uint32_t lmb[2][2];
    #pragma unroll
    for (int t = 0; t < 2; t++)
        #pragma unroll
        for (int p = 0; p < 2; p++)
            lmb[t][p] = sbase + t * B_TERM + l7 * 128 + (((4 * p + sel) ^ l7) << 4);

    const float2* e2p = (const float2*)emb;
    float2* o2 = (float2*)out;

    // Warp-autonomous 16-row chunks (no block sync in the mainloop).
    const int gw = blockIdx.x * (THREADS / 32) + w;

    for (int chunk = gw; chunk < NCHUNKS; chunk += NWARPS_T) {
        const int rlo = chunk * 16 + g;                 // frag rows: rlo, rlo+8
        const int b   = rlo >> 12;
        const int nlo = rlo & 4095;
        const float* xb = x + (size_t)b * 262144;

        // x values this thread owns (mma A layout).
        float xg[16], xh[16];
        #pragma unroll
        for (int ks = 0; ks < 4; ks++)
            #pragma unroll
            for (int j = 0; j < 4; j++) {
                const int c = ks * 16 + tig * 2 + (j & 1) + ((j >> 1) << 3);
                xg[ks * 4 + j] = __ldg(&xb[(size_t)c * 4096 + nlo]);
                xh[ks * 4 + j] = __ldg(&xb[(size_t)c * 4096 + nlo + 8]);
            }

        // A fragments: 2 terms x 4 ksteps x 4 regs.
        uint32_t A1[16], A2[16];
        #pragma unroll
        for (int ks = 0; ks < 4; ks++) {
            uint16_t h0, l0, h1, l1;
            split2(xg[ks*4+0], h0, l0); split2(xg[ks*4+1], h1, l1);
            A1[ks*4+0] = (uint32_t)h0 | ((uint32_t)h1 << 16);
            A2[ks*4+0] = (uint32_t)l0 | ((uint32_t)l1 << 16);
            split2(xh[ks*4+0], h0, l0); split2(xh[ks*4+1], h1, l1);
            A1[ks*4+1] = (uint32_t)h0 | ((uint32_t)h1 << 16);
            A2[ks*4+1] = (uint32_t)l0 | ((uint32_t)l1 << 16);
            split2(xg[ks*4+2], h0, l0); split2(xg[ks*4+3], h1, l1);
            A1[ks*4+2] = (uint32_t)h0 | ((uint32_t)h1 << 16);
            A2[ks*4+2] = (uint32_t)l0 | ((uint32_t)l1 << 16);
            split2(xh[ks*4+2], h0, l0); split2(xh[ks*4+3], h1, l1);
            A1[ks*4+3] = (uint32_t)h0 | ((uint32_t)h1 << 16);
            A2[ks*4+3] = (uint32_t)l0 | ((uint32_t)l1 << 16);
        }

        uint32_t K1l = 0xFFFFFFFFu, K2l = 0xFFFFFFFFu, K3l = 0xFFFFFFFFu;
        uint32_t K1h = 0xFFFFFFFFu, K2h = 0xFFFFFFFFu, K3h = 0xFFFFFFFFu;

        // Two 8-code streams per iteration; 32 MMAs across 4 accumulator chains.
        #pragma unroll 1
        for (int nc = 0; nc < 64; nc += 2) {
            const uint32_t coA = (uint32_t)nc << 10;
            const uint32_t coB = coA + 1024;
            uint32_t BhA[8], BlA[8], BhB[8], BlB[8];
            ldm4(BhA[0], BhA[1], BhA[2], BhA[3], lmb[0][0] + coA);
            ldm4(BhA[4], BhA[5], BhA[6], BhA[7], lmb[0][1] + coA);
            ldm4(BlA[0], BlA[1], BlA[2], BlA[3], lmb[1][0] + coA);
            ldm4(BlA[4], BlA[5], BlA[6], BlA[7], lmb[1][1] + coA);
            ldm4(BhB[0], BhB[1], BhB[2], BhB[3], lmb[0][0] + coB);
            ldm4(BhB[4], BhB[5], BhB[6], BhB[7], lmb[0][1] + coB);
            ldm4(BlB[0], BlB[1], BlB[2], BlB[3], lmb[1][0] + coB);
            ldm4(BlB[4], BlB[5], BlB[6], BlB[7], lmb[1][1] + coB);

            float DBa0=0,DBa1=0,DBa2=0,DBa3=0, DSa0=0,DSa1=0,DSa2=0,DSa3=0;
            float DBb0=0,DBb1=0,DBb2=0,DBb3=0, DSb0=0,DSb1=0,DSb2=0,DSb3=0;
            #pragma unroll
            for (int ks = 0; ks < 4; ks++) {
                const uint32_t a10=A1[4*ks], a11=A1[4*ks+1], a12=A1[4*ks+2], a13=A1[4*ks+3];
                const uint32_t a20=A2[4*ks], a21=A2[4*ks+1], a22=A2[4*ks+2], a23=A2[4*ks+3];
                // smallest-magnitude first within each DS chain; a/b interleaved
                mma16816(DSa0,DSa1,DSa2,DSa3, a20,a21,a22,a23, BlA[2*ks],BlA[2*ks+1]); // (2,2)
                mma16816(DSb0,DSb1,DSb2,DSb3, a20,a21,a22,a23, BlB[2*ks],BlB[2*ks+1]);
                mma16816(DSa0,DSa1,DSa2,DSa3, a20,a21,a22,a23, BhA[2*ks],BhA[2*ks+1]); // (2,1)
                mma16816(DSb0,DSb1,DSb2,DSb3, a20,a21,a22,a23, BhB[2*ks],BhB[2*ks+1]);
                mma16816(DSa0,DSa1,DSa2,DSa3, a10,a11,a12,a13, BlA[2*ks],BlA[2*ks+1]); // (1,2)
                mma16816(DSb0,DSb1,DSb2,DSb3, a10,a11,a12,a13, BlB[2*ks],BlB[2*ks+1]);
                mma16816(DBa0,DBa1,DBa2,DBa3, a10,a11,a12,a13, BhA[2*ks],BhA[2*ks+1]); // (1,1)
                mma16816(DBb0,DBb1,DBb2,DBb3, a10,a11,a12,a13, BhB[2*ks],BhB[2*ks+1]);
            }

            {
                const float2 sv = esqb2[nc * 4 + tig];
                const uint32_t lA = (uint32_t)nc << 1;
                uint32_t k;
                k = (__float_as_uint(fmaf(-2.0f, DBa0 + DSa0, sv.x)) & 0xFFFFFF80u) | lA;
                INSK(k, K1l, K2l, K3l);
                k = (__float_as_uint(fmaf(-2.0f, DBa1 + DSa1, sv.y)) & 0xFFFFFF80u) | (lA + 1);
                INSK(k, K1l, K2l, K3l);
                k = (__float_as_uint(fmaf(-2.0f, DBa2 + DSa2, sv.x)) & 0xFFFFFF80u) | lA;
                INSK(k, K1h, K2h, K3h);
                k = (__float_as_uint(fmaf(-2.0f, DBa3 + DSa3, sv.y)) & 0xFFFFFF80u) | (lA + 1);
                INSK(k, K1h, K2h, K3h);
            }
            {
                const float2 sv = esqb2[(nc + 1) * 4 + tig];
                const uint32_t lB = (uint32_t)(nc + 1) << 1;
                uint32_t k;
                k = (__float_as_uint(fmaf(-2.0f, DBb0 + DSb0, sv.x)) & 0xFFFFFF80u) | lB;
                INSK(k, K1l, K2l, K3l);
                k = (__float_as_uint(fmaf(-2.0f, DBb1 + DSb1, sv.y)) & 0xFFFFFF80u) | (lB + 1);
                INSK(k, K1l, K2l, K3l);
                k = (__float_as_uint(fmaf(-2.0f, DBb2 + DSb2, sv.x)) & 0xFFFFFF80u) | lB;
                INSK(k, K1h, K2h, K3h);
                k = (__float_as_uint(fmaf(-2.0f, DBb3 + DSb3, sv.y)) & 0xFFFFFF80u) | (lB + 1);
                INSK(k, K1h, K2h, K3h);
            }
        }

        // Unpack lane-local top-3, merge exactly across the 4 lanes of the group.
        float b1l, b2l, b3l, b1h, b2h, b3h;
        int   i1l, i2l, i3l, i1h, i2h, i3h;
        unpack_key(K1l, tig, b1l, i1l); unpack_key(K2l, tig, b2l, i2l);
        unpack_key(K3l, tig, b3l, i3l);
        unpack_key(K1h, tig, b1h, i1h); unpack_key(K2h, tig, b2h, i2h);
        unpack_key(K3h, tig, b3h, i3h);
        MRG3(1, b1l, i1l, b2l, i2l, b3l, i3l); MRG3(2, b1l, i1l, b2l, i2l, b3l, i3l);
        MRG3(1, b1h, i1h, b2h, i2h, b3h, i3h); MRG3(2, b1h, i1h, b2h, i2h, b3h, i3h);

        // Ambiguity fallback: exact fp32 re-rank of the top-3 candidates.
        const bool trl = (b2l - b1l) < GAP_THRESH;
        const bool trh = (b2h - b1h) < GAP_THRESH;
        if (__ballot_sync(0xffffffffu, trl || trh)) {
            {
                const float dA = fmaf(-2.0f, exact_dot(e2p, i1l, xg, tig), esqb[i1l]);
                const float dB = fmaf(-2.0f, exact_dot(e2p, i2l, xg, tig), esqb[i2l]);
                const float dC = fmaf(-2.0f, exact_dot(e2p, i3l, xg, tig), esqb[i3l]);
                int   bi = i1l; float bd = dA;
                if ((dB < bd) || (dB == bd && i2l < bi)) { bd = dB; bi = i2l; }
                if ((dC < bd) || (dC == bd && i3l < bi)) { bd = dC; bi = i3l; }
                if (trl) i1l = bi;
            }
            {
                const float dA = fmaf(-2.0f, exact_dot(e2p, i1h, xh, tig), esqb[i1h]);
                const float dB = fmaf(-2.0f, exact_dot(e2p, i2h, xh, tig), esqb[i2h]);
                const float dC = fmaf(-2.0f, exact_dot(e2p, i3h, xh, tig), esqb[i3h]);
                int   bi = i1h; float bd = dA;
                if ((dB < bd) || (dB == bd && i2h < bi)) { bd = dB; bi = i2h; }
                if ((dC < bd) || (dC == bd && i3h < bi)) { bd = dC; bi = i3h; }
                if (trh) i1h = bi;
            }
        }

        // Straight-through output: out = x + (e - x), fp32.
        {
            const size_t obl = (size_t)rlo * 32;
            const size_t obh = (size_t)(rlo + 8) * 32;
            #pragma unroll
            for (int ks = 0; ks < 4; ks++) {
                float2 e0 = __ldg(&e2p[i1l * 32 + ks * 8 + tig]);
                float2 e1 = __ldg(&e2p[i1l * 32 + ks * 8 + tig + 4]);
                float2 v;
                v.x = xg[ks*4+0] + (e0.x - xg[ks*4+0]);
                v.y = xg[ks*4+1] + (e0.y - xg[ks*4+1]);
                o2[obl + ks * 8 + tig] = v;
                v.x = xg[ks*4+2] + (e1.x - xg[ks*4+2]);
                v.y = xg[ks*4+3] + (e1.y - xg[ks*4+3]);
                o2[obl + ks * 8 + tig + 4] = v;

                e0 = __ldg(&e2p[i1h * 32 + ks * 8 + tig]);
                e1 = __ldg(&e2p[i1h * 32 + ks * 8 + tig + 4]);
                v.x = xh[ks*4+0] + (e0.x - xh[ks*4+0]);
                v.y = xh[ks*4+1] + (e0.y - xh[ks*4+1]);
                o2[obh + ks * 8 + tig] = v;
                v.x = xh[ks*4+2] + (e1.x - xh[ks*4+2]);
                v.y = xh[ks*4+3] + (e1.y - xh[ks*4+3]);
                o2[obh + ks * 8 + tig + 4] = v;
            }
        }
    }
}

extern "C" void kernel_launch(void* const* d_in, const int* in_sizes, int n_in,
                              void* d_out, int out_size)
{
    const float* x   = (const float*)d_in[0];
    const float* emb = (const float*)d_in[1];
    float* out = (float*)d_out;

    cudaFuncSetAttribute(vq_mma_kernel,
                         cudaFuncAttributeMaxDynamicSharedMemorySize, SMEM_TOTAL);
    vq_mma_kernel<<<GRIDSZ, THREADS, SMEM_TOTAL>>>(x, emb, out);
}

// round 11
// speedup vs baseline: 2.0735x; 1.1503x over previous
#include <cuda_runtime.h>
#include <cuda_bf16.h>
#include <cstdint>

// VQ nearest-code lookup via mma.sync bf16 3-pass fp32 emulation (2-term splits,
// lo*lo pass dropped into the recheck error budget).
// Packed-key (IMNMX) top-3 tracking + exact fp32 recheck on ambiguous gaps.
// x:   [32, 64, 64, 64] fp32 -> row r = b*4096 + n; elem (r,c) at x[b*262144 + c*4096 + n]
// emb: [512, 64] fp32
// out: flat [131072, 64] fp32 row-major.

#define THREADS  384
#define NCHUNKS  8192          // 131072 rows / 16 rows per warp-chunk
#define GRIDSZ   148
#define NWARPS_T (GRIDSZ * (THREADS / 32))
#define B_TERM   65536         // one bf16 codebook term: 512 rows x 128B
#define SM_ESQ   (2 * B_TERM)
#define SMEM_TOTAL (2 * B_TERM + 2048)
#define BIAS     256.0f
// E_max ~ 1e-2 (3-pass emulation, coherent worst case, incl. dropped lo*lo)
// + 3.9e-3 key truncation. Threshold must exceed 2*E_max; 4e-2 gives margin.
#define GAP_THRESH 4.0e-2f

__device__ __forceinline__ uint32_t smem_u32(const void* p) {
    uint32_t a;
    asm("{ .reg .u64 t; cvta.to.shared.u64 t, %1; cvt.u32.u64 %0, t; }" : "=r"(a) : "l"(p));
    return a;
}

__device__ __forceinline__ void mma16816(float& d0, float& d1, float& d2, float& d3,
                                         uint32_t a0, uint32_t a1, uint32_t a2, uint32_t a3,
                                         uint32_t b0, uint32_t b1) {
    asm("mma.sync.aligned.m16n8k16.row.col.f32.bf16.bf16.f32 "
        "{%0,%1,%2,%3}, {%4,%5,%6,%7}, {%8,%9}, {%0,%1,%2,%3};"
        : "+f"(d0), "+f"(d1), "+f"(d2), "+f"(d3)
        : "r"(a0), "r"(a1), "r"(a2), "r"(a3), "r"(b0), "r"(b1));
}

__device__ __forceinline__ void ldm4(uint32_t& r0, uint32_t& r1, uint32_t& r2, uint32_t& r3,
                                     uint32_t addr) {
    asm volatile("ldmatrix.sync.aligned.m8n8.x4.shared.b16 {%0,%1,%2,%3}, [%4];"
                 : "=r"(r0), "=r"(r1), "=r"(r2), "=r"(r3) : "r"(addr));
}

// Exact 2-term bf16 split (round-and-subtract residual exact in fp32).
__device__ __forceinline__ void split2(float v, uint16_t& h, uint16_t& l) {
    __nv_bfloat16 bh = __float2bfloat16_rn(v);
    float r = v - __bfloat162float(bh);
    __nv_bfloat16 bl = __float2bfloat16_rn(r);
    h = __bfloat16_as_ushort(bh); l = __bfloat16_as_ushort(bl);
}

// Packed-key top-3 insert: pure min/max sorting network (keeps B1<=B2<=B3).
#define INSK(k_, B1_, B2_, B3_) do {                          \
    uint32_t _t1 = max((B1_), (k_)); B1_ = min((B1_), (k_));  \
    uint32_t _t2 = max((B2_), _t1);  B2_ = min((B2_), _t1);   \
    B3_ = min((B3_), _t2);                                    \
} while (0)

// Lexicographic insert (tie -> smaller index), for cross-lane merges.
#define INS3(m_, n_, B1_, I1_, B2_, I2_, B3_, I3_) do {                   \
    bool _l1 = ((m_) < (B1_)) || ((m_) == (B1_) && (n_) < (I1_));         \
    bool _l2 = ((m_) < (B2_)) || ((m_) == (B2_) && (n_) < (I2_));         \
    bool _l3 = ((m_) < (B3_)) || ((m_) == (B3_) && (n_) < (I3_));         \
    B3_ = _l2 ? (B2_) : (_l3 ? (m_) : (B3_));                             \
    I3_ = _l2 ? (I2_) : (_l3 ? (n_) : (I3_));                             \
    B2_ = _l1 ? (B1_) : (_l2 ? (m_) : (B2_));                             \
    I2_ = _l1 ? (I1_) : (_l2 ? (n_) : (I2_));                             \
    B1_ = _l1 ? (m_) : (B1_);                                             \
    I1_ = _l1 ? (n_) : (I1_);                                             \
} while (0)

#define MRG3(off, B1_, I1_, B2_, I2_, B3_, I3_) do {                      \
    float _o1 = __shfl_xor_sync(0xffffffffu, B1_, off);                   \
    int   _j1 = __shfl_xor_sync(0xffffffffu, I1_, off);                   \
    float _o2 = __shfl_xor_sync(0xffffffffu, B2_, off);                   \
    int   _j2 = __shfl_xor_sync(0xffffffffu, I2_, off);                   \
    float _o3 = __shfl_xor_sync(0xffffffffu, B3_, off);                   \
    int   _j3 = __shfl_xor_sync(0xffffffffu, I3_, off);                   \
    INS3(_o1, _j1, B1_, I1_, B2_, I2_, B3_, I3_);                         \
    INS3(_o2, _j2, B1_, I1_, B2_, I2_, B3_, I3_);                         \
    INS3(_o3, _j3, B1_, I1_, B2_, I2_, B3_, I3_);                         \
} while (0)

// Exact fp32 dot of row (xr, 16 vals, mma layout) with code c; quad-reduced.
__device__ __forceinline__ float exact_dot(const float2* __restrict__ e2p,
                                           int c, const float* xr, int tig) {
    float s = 0.0f;
    #pragma unroll
    for (int ks = 0; ks < 4; ks++) {
        float2 e0 = __ldg(&e2p[c * 32 + ks * 8 + tig]);
        float2 e1 = __ldg(&e2p[c * 32 + ks * 8 + tig + 4]);
        s = fmaf(xr[ks*4+0], e0.x, s); s = fmaf(xr[ks*4+1], e0.y, s);
        s = fmaf(xr[ks*4+2], e1.x, s); s = fmaf(xr[ks*4+3], e1.y, s);
    }
    s += __shfl_xor_sync(0xffffffffu, s, 1);
    s += __shfl_xor_sync(0xffffffffu, s, 2);
    return s;
}

// Unpack a packed key: biased truncated value + global code index.
__device__ __forceinline__ void unpack_key(uint32_t key, int tig, float& v, int& n) {
    v = __uint_as_float(key & 0xFFFFFF80u);
    const int l = key & 127;
    n = (l >> 1) * 8 + 2 * tig + (l & 1);
}

__global__ void __launch_bounds__(THREADS, 1)
vq_mma_kernel(const float* __restrict__ x, const float* __restrict__ emb,
              float* __restrict__ out)
{
    extern __shared__ char sm[];
    float* esqb = (float*)(sm + SM_ESQ);      // e_sq + BIAS
    const float2* esqb2 = (const float2*)esqb;
    const uint32_t sbase = smem_u32(sm);

    const int tid  = threadIdx.x;
    const int w    = tid >> 5;
    const int lane = tid & 31;
    const int g    = lane >> 2;     // row within 8
    const int tig  = lane & 3;      // thread in group

    // ---- Stage codebook: 2 bf16 terms, ldmatrix XOR swizzle ----
    for (int idx = tid; idx < 512 * 64; idx += THREADS) {
        const int n = idx >> 6, k = idx & 63;
        uint16_t h, l;
        split2(__ldg(&emb[idx]), h, l);
        const uint32_t o = (uint32_t)(n * 128 + ((((k >> 3) ^ (n & 7))) << 4) + ((k & 7) << 1));
        *(uint16_t*)(sm + o)          = h;
        *(uint16_t*)(sm + B_TERM + o) = l;
    }
    for (int n = tid; n < 512; n += THREADS) {
        float s = 0.0f;
        #pragma unroll
        for (int k = 0; k < 64; k++) { float v = __ldg(&emb[n * 64 + k]); s = fmaf(v, v, s); }
        esqb[n] = s + BIAS;
    }
    __syncthreads();

    // ldmatrix base addresses: term t, k-pair p.
    const int l7 = lane & 7, sel = lane >> 3;
    uint32_t lmb[2][2];
    #pragma unroll
    for (int t = 0; t < 2; t++)
        #pragma unroll
        for (int p = 0; p < 2; p++)
            lmb[t][p] = sbase + t * B_TERM + l7 * 128 + (((4 * p + sel) ^ l7) << 4);

    const float2* e2p = (const float2*)emb;
    float2* o2 = (float2*)out;

    // Warp-autonomous 16-row chunks (no block sync in the mainloop).
    const int gw = blockIdx.x * (THREADS / 32) + w;

    for (int chunk = gw; chunk < NCHUNKS; chunk += NWARPS_T) {
        const int rlo = chunk * 16 + g;                 // frag rows: rlo, rlo+8
        const int b   = rlo >> 12;
        const int nlo = rlo & 4095;
        const float* xb = x + (size_t)b * 262144;

        // x values this thread owns (mma A layout).
        float xg[16], xh[16];
        #pragma unroll
        for (int ks = 0; ks < 4; ks++)
            #pragma unroll
            for (int j = 0; j < 4; j++) {
                const int c = ks * 16 + tig * 2 + (j & 1) + ((j >> 1) << 3);
                xg[ks * 4 + j] = __ldg(&xb[(size_t)c * 4096 + nlo]);
                xh[ks * 4 + j] = __ldg(&xb[(size_t)c * 4096 + nlo + 8]);
            }

        // A fragments: 2 terms x 4 ksteps x 4 regs.
        uint32_t A1[16], A2[16];
        #pragma unroll
        for (int ks = 0; ks < 4; ks++) {
            uint16_t h0, l0, h1, l1;
            split2(xg[ks*4+0], h0, l0); split2(xg[ks*4+1], h1, l1);
            A1[ks*4+0] = (uint32_t)h0 | ((uint32_t)h1 << 16);
            A2[ks*4+0] = (uint32_t)l0 | ((uint32_t)l1 << 16);
            split2(xh[ks*4+0], h0, l0); split2(xh[ks*4+1], h1, l1);
            A1[ks*4+1] = (uint32_t)h0 | ((uint32_t)h1 << 16);
            A2[ks*4+1] = (uint32_t)l0 | ((uint32_t)l1 << 16);
            split2(xg[ks*4+2], h0, l0); split2(xg[ks*4+3], h1, l1);
            A1[ks*4+2] = (uint32_t)h0 | ((uint32_t)h1 << 16);
            A2[ks*4+2] = (uint32_t)l0 | ((uint32_t)l1 << 16);
            split2(xh[ks*4+2], h0, l0); split2(xh[ks*4+3], h1, l1);
            A1[ks*4+3] = (uint32_t)h0 | ((uint32_t)h1 << 16);
            A2[ks*4+3] = (uint32_t)l0 | ((uint32_t)l1 << 16);
        }

        uint32_t K1l = 0xFFFFFFFFu, K2l = 0xFFFFFFFFu, K3l = 0xFFFFFFFFu;
        uint32_t K1h = 0xFFFFFFFFu, K2h = 0xFFFFFFFFu, K3h = 0xFFFFFFFFu;

        // Two 8-code streams per iteration; 24 MMAs across 4 accumulator chains.
        // Passes: (2,1), (1,2) -> DS chain; (1,1) -> DB chain. (2,2) dropped
        // into the recheck error budget.
        #pragma unroll 1
        for (int nc = 0; nc < 64; nc += 2) {
            const uint32_t coA = (uint32_t)nc << 10;
            const uint32_t coB = coA + 1024;
            uint32_t BhA[8], BlA[8], BhB[8], BlB[8];
            ldm4(BhA[0], BhA[1], BhA[2], BhA[3], lmb[0][0] + coA);
            ldm4(BhA[4], BhA[5], BhA[6], BhA[7], lmb[0][1] + coA);
            ldm4(BlA[0], BlA[1], BlA[2], BlA[3], lmb[1][0] + coA);
            ldm4(BlA[4], BlA[5], BlA[6], BlA[7], lmb[1][1] + coA);
            ldm4(BhB[0], BhB[1], BhB[2], BhB[3], lmb[0][0] + coB);
            ldm4(BhB[4], BhB[5], BhB[6], BhB[7], lmb[0][1] + coB);
            ldm4(BlB[0], BlB[1], BlB[2], BlB[3], lmb[1][0] + coB);
            ldm4(BlB[4], BlB[5], BlB[6], BlB[7], lmb[1][1] + coB);

            float DBa0=0,DBa1=0,DBa2=0,DBa3=0, DSa0=0,DSa1=0,DSa2=0,DSa3=0;
            float DBb0=0,DBb1=0,DBb2=0,DBb3=0, DSb0=0,DSb1=0,DSb2=0,DSb3=0;
            #pragma unroll
            for (int ks = 0; ks < 4; ks++) {
                const uint32_t a10=A1[4*ks], a11=A1[4*ks+1], a12=A1[4*ks+2], a13=A1[4*ks+3];
                const uint32_t a20=A2[4*ks], a21=A2[4*ks+1], a22=A2[4*ks+2], a23=A2[4*ks+3];
                // order maximizes issue distance between dependent MMAs
                mma16816(DSa0,DSa1,DSa2,DSa3, a20,a21,a22,a23, BhA[2*ks],BhA[2*ks+1]); // (2,1) A
                mma16816(DSb0,DSb1,DSb2,DSb3, a20,a21,a22,a23, BhB[2*ks],BhB[2*ks+1]); // (2,1) B
                mma16816(DBa0,DBa1,DBa2,DBa3, a10,a11,a12,a13, BhA[2*ks],BhA[2*ks+1]); // (1,1) A
                mma16816(DBb0,DBb1,DBb2,DBb3, a10,a11,a12,a13, BhB[2*ks],BhB[2*ks+1]); // (1,1) B
                mma16816(DSa0,DSa1,DSa2,DSa3, a10,a11,a12,a13, BlA[2*ks],BlA[2*ks+1]); // (1,2) A
                mma16816(DSb0,DSb1,DSb2,DSb3, a10,a11,a12,a13, BlB[2*ks],BlB[2*ks+1]); // (1,2) B
            }

            {
                const float2 sv = esqb2[nc * 4 + tig];
                const uint32_t lA = (uint32_t)nc << 1;
                uint32_t k;
                k = (__float_as_uint(fmaf(-2.0f, DBa0 + DSa0, sv.x)) & 0xFFFFFF80u) | lA;
                INSK(k, K1l, K2l, K3l);
                k = (__float_as_uint(fmaf(-2.0f, DBa1 + DSa1, sv.y)) & 0xFFFFFF80u) | (lA + 1);
                INSK(k, K1l, K2l, K3l);
                k = (__float_as_uint(fmaf(-2.0f, DBa2 + DSa2, sv.x)) & 0xFFFFFF80u) | lA;
                INSK(k, K1h, K2h, K3h);
                k = (__float_as_uint(fmaf(-2.0f, DBa3 + DSa3, sv.y)) & 0xFFFFFF80u) | (lA + 1);
                INSK(k, K1h, K2h, K3h);
            }
            {
                const float2 sv = esqb2[(nc + 1) * 4 + tig];
                const uint32_t lB = (uint32_t)(nc + 1) << 1;
                uint32_t k;
                k = (__float_as_uint(fmaf(-2.0f, DBb0 + DSb0, sv.x)) & 0xFFFFFF80u) | lB;
                INSK(k, K1l, K2l, K3l);
                k = (__float_as_uint(fmaf(-2.0f, DBb1 + DSb1, sv.y)) & 0xFFFFFF80u) | (lB + 1);
                INSK(k, K1l, K2l, K3l);
                k = (__float_as_uint(fmaf(-2.0f, DBb2 + DSb2, sv.x)) & 0xFFFFFF80u) | lB;
                INSK(k, K1h, K2h, K3h);
                k = (__float_as_uint(fmaf(-2.0f, DBb3 + DSb3, sv.y)) & 0xFFFFFF80u) | (lB + 1);
                INSK(k, K1h, K2h, K3h);
            }
        }

        // Unpack lane-local top-3, merge exactly across the 4 lanes of the group.
        float b1l, b2l, b3l, b1h, b2h, b3h;
        int   i1l, i2l, i3l, i1h, i2h, i3h;
        unpack_key(K1l, tig, b1l, i1l); unpack_key(K2l, tig, b2l, i2l);
        unpack_key(K3l, tig, b3l, i3l);
        unpack_key(K1h, tig, b1h, i1h); unpack_key(K2h, tig, b2h, i2h);
        unpack_key(K3h, tig, b3h, i3h);
        MRG3(1, b1l, i1l, b2l, i2l, b3l, i3l); MRG3(2, b1l, i1l, b2l, i2l, b3l, i3l);
        MRG3(1, b1h, i1h, b2h, i2h, b3h, i3h); MRG3(2, b1h, i1h, b2h, i2h, b3h, i3h);

        // Ambiguity fallback: exact fp32 re-rank of the top-3 candidates.
        const bool trl = (b2l - b1l) < GAP_THRESH;
        const bool trh = (b2h - b1h) < GAP_THRESH;
        if (__ballot_sync(0xffffffffu, trl || trh)) {
            {
                const float dA = fmaf(-2.0f, exact_dot(e2p, i1l, xg, tig), esqb[i1l]);
                const float dB = fmaf(-2.0f, exact_dot(e2p, i2l, xg, tig), esqb[i2l]);
                const float dC = fmaf(-2.0f, exact_dot(e2p, i3l, xg, tig), esqb[i3l]);
                int   bi = i1l; float bd = dA;
                if ((dB < bd) || (dB == bd && i2l < bi)) { bd = dB; bi = i2l; }
                if ((dC < bd) || (dC == bd && i3l < bi)) { bd = dC; bi = i3l; }
                if (trl) i1l = bi;
            }
            {
                const float dA = fmaf(-2.0f, exact_dot(e2p, i1h, xh, tig), esqb[i1h]);
                const float dB = fmaf(-2.0f, exact_dot(e2p, i2h, xh, tig), esqb[i2h]);
                const float dC = fmaf(-2.0f, exact_dot(e2p, i3h, xh, tig), esqb[i3h]);
                int   bi = i1h; float bd = dA;
                if ((dB < bd) || (dB == bd && i2h < bi)) { bd = dB; bi = i2h; }
                if ((dC < bd) || (dC == bd && i3h < bi)) { bd = dC; bi = i3h; }
                if (trh) i1h = bi;
            }
        }

        // Straight-through output: out = x + (e - x), fp32.
        {
            const size_t obl = (size_t)rlo * 32;
            const size_t obh = (size_t)(rlo + 8) * 32;
            #pragma unroll
            for (int ks = 0; ks < 4; ks++) {
                float2 e0 = __ldg(&e2p[i1l * 32 + ks * 8 + tig]);
                float2 e1 = __ldg(&e2p[i1l * 32 + ks * 8 + tig + 4]);
                float2 v;
                v.x = xg[ks*4+0] + (e0.x - xg[ks*4+0]);
                v.y = xg[ks*4+1] + (e0.y - xg[ks*4+1]);
                o2[obl + ks * 8 + tig] = v;
                v.x = xg[ks*4+2] + (e1.x - xg[ks*4+2]);
                v.y = xg[ks*4+3] + (e1.y - xg[ks*4+3]);
                o2[obl + ks * 8 + tig + 4] = v;

                e0 = __ldg(&e2p[i1h * 32 + ks * 8 + tig]);
                e1 = __ldg(&e2p[i1h * 32 + ks * 8 + tig + 4]);
                v.x = xh[ks*4+0] + (e0.x - xh[ks*4+0]);
                v.y = xh[ks*4+1] + (e0.y - xh[ks*4+1]);
                o2[obh + ks * 8 + tig] = v;
                v.x = xh[ks*4+2] + (e1.x - xh[ks*4+2]);
                v.y = xh[ks*4+3] + (e1.y - xh[ks*4+3]);
                o2[obh + ks * 8 + tig + 4] = v;
            }
        }
    }
}

extern "C" void kernel_launch(void* const* d_in, const int* in_sizes, int n_in,
                              void* d_out, int out_size)
{
    const float* x   = (const float*)d_in[0];
    const float* emb = (const float*)d_in[1];
    float* out = (float*)d_out;

    cudaFuncSetAttribute(vq_mma_kernel,
                         cudaFuncAttributeMaxDynamicSharedMemorySize, SMEM_TOTAL);
    vq_mma_kernel<<<GRIDSZ, THREADS, SMEM_TOTAL>>>(x, emb, out);
}